// round 3
// baseline (speedup 1.0000x reference)
#include <cuda_runtime.h>

// EfficientPWL, intercept form: out = x * a[i1] + b[i1]
// a[i1] = slopes[c, i1], b[i1] = cumbias[c, i2] - cp[i2]*slopes[c, i1],
// i2 = max(i1-1,0), uniform breakpoints linspace(-1,1,33), dt = 1/16.
//
// B=32, C=128, T=8192.
// Grid = 1024 blocks, each handling 4 rows of the SAME channel c:
//   rows (4*b4 + k)*128 + c,  k = 0..3,  where c = bid & 127, b4 = bid >> 7.
// 1024 blocks < 1184 concurrent (8/SM x 148) -> single wave, 6.92 blocks/SM,
// per-SM quantization only 1.2% (vs 15.6% wave-ceil with grid=4096).

#define CCH     128
#define TLEN    8192
#define NCP     33
#define NSL     34
#define THREADS 256
#define ROWS_PB 4
#define F4_ROW  (TLEN / 4)          // 2048 float4 per row

__global__ void __launch_bounds__(THREADS, 8)
efficient_pwl_kernel(const float* __restrict__ x,
                     const float* __restrict__ slopes,
                     const float* __restrict__ biases,
                     float* __restrict__ out) {
    __shared__ float  s_slope[NSL];
    __shared__ float  s_cumb[NCP];
    __shared__ float2 s_tab[NSL];   // (a, b) per bucket index i1

    const int bid = blockIdx.x;
    const int c   = bid & (CCH - 1);
    const int b4  = bid >> 7;       // group of 4 batch indices
    const int tid = threadIdx.x;

    if (tid < NSL)
        s_slope[tid] = slopes[c * NSL + tid];
    __syncthreads();

    if (tid == 0) {
        const float dt = 0.0625f;
        float acc = biases[c];
        s_cumb[0] = acc;
        #pragma unroll
        for (int j = 1; j < NCP; j++) {
            acc = fmaf(s_slope[j], dt, acc);
            s_cumb[j] = acc;
        }
    }
    __syncthreads();

    if (tid < NSL) {
        const int i2 = max(tid - 1, 0);
        const float cp = -1.0f + 0.0625f * (float)i2;
        const float a  = s_slope[tid];
        s_tab[tid] = make_float2(a, fmaf(-cp, a, s_cumb[i2]));
    }
    __syncthreads();

    #pragma unroll
    for (int k = 0; k < ROWS_PB; k++) {
        const size_t row = (size_t)(b4 * ROWS_PB + k) * CCH + c;
        const float4* __restrict__ xin = (const float4*)(x + row * TLEN);
        float4* __restrict__ o         = (float4*)(out + row * TLEN);

        // 2048 float4 / 256 threads = 8 per thread; two groups of 4
        // front-batched loads (MLP=4) to stay within the 32-reg budget.
        #pragma unroll
        for (int g = 0; g < 2; g++) {
            float4 v[4];
            #pragma unroll
            for (int i = 0; i < 4; i++)
                v[i] = __ldcs(&xin[tid + (g * 4 + i) * THREADS]);

            #pragma unroll
            for (int i = 0; i < 4; i++) {
                float4 r;
                #pragma unroll
                for (int j = 0; j < 4; j++) {
                    const float xv = (&v[i].x)[j];
                    int i1 = __float2int_rd(fmaf(xv, 16.0f, 16.0f)) + 1;
                    i1 = max(0, min(NCP, i1));
                    const float2 ab = s_tab[i1];
                    (&r.x)[j] = fmaf(xv, ab.x, ab.y);
                }
                __stcs(&o[tid + (g * 4 + i) * THREADS], r);
            }
        }
    }
}

extern "C" void kernel_launch(void* const* d_in, const int* in_sizes, int n_in,
                              void* d_out, int out_size) {
    const float* x      = (const float*)d_in[0];
    const float* slopes = (const float*)d_in[1];
    const float* biases = (const float*)d_in[2];
    float* out          = (float*)d_out;

    efficient_pwl_kernel<<<1024, THREADS>>>(x, slopes, biases, out);
}

// round 7
// speedup vs baseline: 1.0976x; 1.0976x over previous
#include <cuda_runtime.h>

// EfficientPWL, intercept form: out = x * a[i1] + b[i1]
// a[i1] = slopes[c, i1], b[i1] = cumbias[c, i2] - cp[i2]*slopes[c, i1],
// i2 = max(i1-1,0), uniform breakpoints linspace(-1,1,33), dt = 1/16.
//
// B=32, C=128, T=8192.
// Grid = 8192: each block handles HALF a row (32KB traffic, ~5us lifetime)
// to shorten the end-of-kernel DRAM ramp-down (finer drain granularity).

#define CCH     128
#define TLEN    8192
#define NCP     33
#define NSL     34
#define THREADS 256
#define VPT     4                    // float4 per thread (half row)
#define F4_HALF (TLEN / 8)           // 1024 float4 per half-row

__global__ void __launch_bounds__(THREADS, 8)
efficient_pwl_kernel(const float* __restrict__ x,
                     const float* __restrict__ slopes,
                     const float* __restrict__ biases,
                     float* __restrict__ out) {
    __shared__ float  s_slope[NSL];
    __shared__ float  s_cumb[NCP];
    __shared__ float2 s_tab[NSL];   // (a, b) per bucket index i1

    const int bid  = blockIdx.x;
    const int row  = bid >> 1;          // b*C + c
    const int half = bid & 1;
    const int c    = row & (CCH - 1);
    const int tid  = threadIdx.x;

    if (tid < NSL)
        s_slope[tid] = slopes[c * NSL + tid];
    __syncthreads();

    if (tid == 0) {
        const float dt = 0.0625f;
        float acc = biases[c];
        s_cumb[0] = acc;
        #pragma unroll
        for (int j = 1; j < NCP; j++) {
            acc = fmaf(s_slope[j], dt, acc);
            s_cumb[j] = acc;
        }
    }
    __syncthreads();

    if (tid < NSL) {
        const int i2 = max(tid - 1, 0);
        const float cp = -1.0f + 0.0625f * (float)i2;
        const float a  = s_slope[tid];
        s_tab[tid] = make_float2(a, fmaf(-cp, a, s_cumb[i2]));
    }
    __syncthreads();

    const size_t base = (size_t)row * TLEN + (size_t)half * (TLEN / 2);
    const float4* __restrict__ xin = (const float4*)(x + base);
    float4* __restrict__ o         = (float4*)(out + base);

    // Front-batched loads (MLP = 4 per thread), then compute + store.
    float4 v[VPT];
    #pragma unroll
    for (int i = 0; i < VPT; i++)
        v[i] = xin[tid + i * THREADS];

    #pragma unroll
    for (int i = 0; i < VPT; i++) {
        float4 r;
        #pragma unroll
        for (int j = 0; j < 4; j++) {
            const float xv = (&v[i].x)[j];
            int i1 = __float2int_rd(fmaf(xv, 16.0f, 16.0f)) + 1;
            i1 = max(0, min(NCP, i1));
            const float2 ab = s_tab[i1];
            (&r.x)[j] = fmaf(xv, ab.x, ab.y);
        }
        o[tid + i * THREADS] = r;
    }
}

extern "C" void kernel_launch(void* const* d_in, const int* in_sizes, int n_in,
                              void* d_out, int out_size) {
    const float* x      = (const float*)d_in[0];
    const float* slopes = (const float*)d_in[1];
    const float* biases = (const float*)d_in[2];
    float* out          = (float*)d_out;

    efficient_pwl_kernel<<<8192, THREADS>>>(x, slopes, biases, out);
}